// round 7
// baseline (speedup 1.0000x reference)
#include <cuda_runtime.h>
#include <math.h>
#include <stdint.h>

#define S_DIM 200
#define H_DIM 128
#define F_DIM 512
#define NH 4
#define ATTP 208
#define NT 512
#define MROWS 208
#define NWARP_C 13
#define BUFQ 65536            // one quarter fragment buffer (128 blocks * 512B)

// smem: [buf0 0..64K][buf1 64K..128K] (X pitch-132 overlaps, dead after A-hoist),
// then duplicated-W2 (u64 pairs), att, outb.
#define SM_W2D   131072                 // 512 cols * 4 heads * 8B = 16384
#define SM_ATT   (SM_W2D + 16384)
#define SM_OUTB  (SM_ATT + 3328)
#define SM_TOTAL (SM_OUTB + 6144)       // 156928 B

typedef unsigned long long u64;

static __device__ __forceinline__ uint32_t smem_u32(const void* p) {
    uint32_t a;
    asm("{ .reg .u64 t; cvta.to.shared.u64 t, %1; cvt.u32.u64 %0, t; }" : "=r"(a) : "l"(p));
    return a;
}
static __device__ __forceinline__ uint32_t f2tf32(float x) {
    uint32_t r; asm("cvt.rna.tf32.f32 %0, %1;" : "=r"(r) : "f"(x)); return r;
}
static __device__ __forceinline__ float fast_tanh(float x) {
    float r; asm("tanh.approx.f32 %0, %1;" : "=f"(r) : "f"(x));
    return r;
}
static __device__ __forceinline__ u64 dup2(float x) {
    u64 r; asm("mov.b64 %0, {%1,%1};" : "=l"(r) : "f"(x)); return r;
}
static __device__ __forceinline__ u64 pack2(float lo, float hi) {
    u64 r; asm("mov.b64 %0, {%1,%2};" : "=l"(r) : "f"(lo), "f"(hi)); return r;
}
static __device__ __forceinline__ void unpack2(u64 v, float& lo, float& hi) {
    asm("mov.b64 {%0,%1}, %2;" : "=f"(lo), "=f"(hi) : "l"(v));
}
static __device__ __forceinline__ void ffma2(u64& d, u64 a, u64 b) {
    asm("fma.rn.f32x2 %0, %1, %2, %0;" : "+l"(d) : "l"(a), "l"(b));
}
static __device__ __forceinline__ void mma_tf32(float* c, const uint32_t* a,
                                                uint32_t b0, uint32_t b1) {
    asm volatile(
        "mma.sync.aligned.m16n8k8.row.col.f32.tf32.tf32.f32 "
        "{%0,%1,%2,%3}, {%4,%5,%6,%7}, {%8,%9}, {%0,%1,%2,%3};"
        : "+f"(c[0]), "+f"(c[1]), "+f"(c[2]), "+f"(c[3])
        : "r"(a[0]), "r"(a[1]), "r"(a[2]), "r"(a[3]), "r"(b0), "r"(b1));
}

// ---- W1 staging: block blk = npair*16 + kf; lane (g,t) slot holds
// {W1[kf8+t][n0+g], W1[kf8+t+4][n0+g], W1[kf8+t][n0+8+g], W1[kf8+t+4][n0+8+g]} tf32
static __device__ __forceinline__ void stage_ldg(float* pv, int ioff, int qcol,
                                                 const float* __restrict__ W1,
                                                 int wid, int g, int t) {
    #pragma unroll
    for (int j = 0; j < 2; j++) {
        int blk = (ioff + j) * 16 + wid;
        int npair = blk >> 4, kf = blk & 15;
        const float* p = W1 + (size_t)(kf * 8 + t) * F_DIM + qcol + npair * 16 + g;
        pv[4 * j + 0] = p[0];
        pv[4 * j + 1] = p[4 * F_DIM];
        pv[4 * j + 2] = p[8];
        pv[4 * j + 3] = p[8 + 4 * F_DIM];
    }
}
static __device__ __forceinline__ void stage_sts(const float* pv, int ioff,
                                                 uint32_t bufb, int wid, int lane) {
    #pragma unroll
    for (int j = 0; j < 2; j++) {
        int blk = (ioff + j) * 16 + wid;
        uint32_t q0 = f2tf32(pv[4 * j + 0]), q1 = f2tf32(pv[4 * j + 1]);
        uint32_t q2 = f2tf32(pv[4 * j + 2]), q3 = f2tf32(pv[4 * j + 3]);
        asm volatile("st.shared.v4.b32 [%0], {%1,%2,%3,%4};"
                     :: "r"(bufb + (uint32_t)blk * 512 + (uint32_t)lane * 16),
                        "r"(q0), "r"(q1), "r"(q2), "r"(q3));
    }
}

static __device__ __forceinline__ void sweep_npp(uint32_t bq, uint32_t w2db, int q, int npp,
                                                 const uint32_t (*A)[4],
                                                 u64* attp, int lane, int t) {
    float acc[2][2][4];
    #pragma unroll
    for (int p = 0; p < 2; p++)
        #pragma unroll
        for (int nf = 0; nf < 2; nf++)
            #pragma unroll
            for (int i = 0; i < 4; i++) acc[p][nf][i] = 0.0f;

    uint32_t base = bq + (uint32_t)(npp * 32) * 512 + (uint32_t)lane * 16;
    #pragma unroll
    for (int kf = 0; kf < 16; kf++) {
        uint32_t x0, x1, x2, x3, y0, y1, y2, y3;
        uint32_t a0 = base + (uint32_t)kf * 512;
        asm volatile("ld.shared.v4.b32 {%0,%1,%2,%3}, [%4];"
                     : "=r"(x0), "=r"(x1), "=r"(x2), "=r"(x3) : "r"(a0));
        asm volatile("ld.shared.v4.b32 {%0,%1,%2,%3}, [%4];"
                     : "=r"(y0), "=r"(y1), "=r"(y2), "=r"(y3) : "r"(a0 + 8192));
        mma_tf32(acc[0][0], A[kf], x0, x1);
        mma_tf32(acc[0][1], A[kf], x2, x3);
        mma_tf32(acc[1][0], A[kf], y0, y1);
        mma_tf32(acc[1][1], A[kf], y2, y3);
    }
    // fused epilogue: tanh.approx + packed f32x2 W2 contraction
    #pragma unroll
    for (int p = 0; p < 2; p++) {
        #pragma unroll
        for (int nf = 0; nf < 2; nf++) {
            int col = q * 128 + (npp * 2 + p) * 16 + nf * 8 + 2 * t;   // even col
            uint32_t wb = w2db + (uint32_t)col * 32;   // 4 u64 per col
            u64 wa0, wa1, wa2, wa3, wb0, wb1, wb2, wb3;
            asm volatile("ld.shared.v2.u64 {%0,%1}, [%2];" : "=l"(wa0), "=l"(wa1) : "r"(wb));
            asm volatile("ld.shared.v2.u64 {%0,%1}, [%2];" : "=l"(wa2), "=l"(wa3) : "r"(wb + 16));
            asm volatile("ld.shared.v2.u64 {%0,%1}, [%2];" : "=l"(wb0), "=l"(wb1) : "r"(wb + 32));
            asm volatile("ld.shared.v2.u64 {%0,%1}, [%2];" : "=l"(wb2), "=l"(wb3) : "r"(wb + 48));
            u64 H0 = pack2(fast_tanh(acc[p][nf][0]), fast_tanh(acc[p][nf][2]));
            u64 H1 = pack2(fast_tanh(acc[p][nf][1]), fast_tanh(acc[p][nf][3]));
            ffma2(attp[0], H0, wa0); ffma2(attp[0], H1, wb0);
            ffma2(attp[1], H0, wa1); ffma2(attp[1], H1, wb1);
            ffma2(attp[2], H0, wa2); ffma2(attp[2], H1, wb2);
            ffma2(attp[3], H0, wa3); ffma2(attp[3], H1, wb3);
        }
    }
}

__global__ __launch_bounds__(NT, 1)
void mha_mma_kernel(const float* __restrict__ item,
                    const int*   __restrict__ mask,
                    const float* __restrict__ pos,
                    const float* __restrict__ W1,
                    const float* __restrict__ W2,
                    float* __restrict__ out)
{
    extern __shared__ char smem[];
    const uint32_t smb = smem_u32(smem);
    uint32_t* xw32 = (uint32_t*)smem;            // X pitch-132, dead after A-hoist
    u64*      w2d  = (u64*)(smem + SM_W2D);
    float*    atts = (float*)(smem + SM_ATT);
    float*    outb = (float*)(smem + SM_OUTB);

    const int tid = threadIdx.x, wid = tid >> 5, lane = tid & 31;
    const int g = lane >> 2, t = lane & 3;
    const int b = blockIdx.x;
    const float* itemb = item + (size_t)b * (S_DIM * H_DIM);

    // ---- Phase 0: X+pos -> smem (tf32), pitch 132. W2 duplicated copy. ----
    for (int idx = tid; idx < MROWS * 128; idx += NT) {
        int row = idx >> 7, h = idx & 127;
        float v = 0.0f;
        if (row < S_DIM) v = itemb[row * 128 + h] + pos[row * 128 + h];
        xw32[row * 132 + h] = f2tf32(v);
    }
    for (int i = tid; i < F_DIM * NH; i += NT) w2d[i] = dup2(W2[i]);
    __syncthreads();

    // ---- Phase 1: prefetch q0 chunk0 (global), hoist A fragments from X ----
    float pv[8];
    stage_ldg(pv, 0, 0, W1, wid, g, t);

    uint32_t A[16][4];
    if (wid < NWARP_C) {
        int r0 = wid * 16 + g;
        #pragma unroll
        for (int kf = 0; kf < 16; kf++) {
            int c0 = kf * 8 + t;
            A[kf][0] = xw32[r0 * 132 + c0];
            A[kf][1] = xw32[(r0 + 8) * 132 + c0];
            A[kf][2] = xw32[r0 * 132 + c0 + 4];
            A[kf][3] = xw32[(r0 + 8) * 132 + c0 + 4];
        }
    }
    __syncthreads();   // all A-hoists done before buf0 overwrites X

    // stage remainder of quarter 0 into buf0
    stage_sts(pv, 0, smb, wid, lane);
    stage_ldg(pv, 2, 0, W1, wid, g, t); stage_sts(pv, 2, smb, wid, lane);
    stage_ldg(pv, 4, 0, W1, wid, g, t); stage_sts(pv, 4, smb, wid, lane);
    stage_ldg(pv, 6, 0, W1, wid, g, t); stage_sts(pv, 6, smb, wid, lane);
    __syncthreads();

    u64 attp[4];
    #pragma unroll
    for (int k = 0; k < 4; k++) attp[k] = pack2(0.0f, 0.0f);

    const uint32_t w2db = smb + SM_W2D;

    // ---- Phase 2: 4 quarters, double-buffered, staging pipelined with sweeps ----
    #pragma unroll 1
    for (int q = 0; q < 4; q++) {
        const uint32_t bq = smb + (uint32_t)(q & 1) * BUFQ;
        const uint32_t bn = smb + (uint32_t)((q + 1) & 1) * BUFQ;
        const int qc = (q + 1) * 128;
        const bool pre = (q < 3);

        if (pre) stage_ldg(pv, 0, qc, W1, wid, g, t);
        if (wid < NWARP_C) sweep_npp(bq, w2db, q, 0, A, attp, lane, t);
        if (pre) { stage_sts(pv, 0, bn, wid, lane); stage_ldg(pv, 2, qc, W1, wid, g, t); }
        if (wid < NWARP_C) sweep_npp(bq, w2db, q, 1, A, attp, lane, t);
        if (pre) { stage_sts(pv, 2, bn, wid, lane); stage_ldg(pv, 4, qc, W1, wid, g, t); }
        if (wid < NWARP_C) sweep_npp(bq, w2db, q, 2, A, attp, lane, t);
        if (pre) { stage_sts(pv, 4, bn, wid, lane); stage_ldg(pv, 6, qc, W1, wid, g, t); }
        if (wid < NWARP_C) sweep_npp(bq, w2db, q, 3, A, attp, lane, t);
        if (pre) stage_sts(pv, 6, bn, wid, lane);
        __syncthreads();
    }

    // ---- Phase 3: reduce att over the 4-lane k-group, write atts ----
    if (wid < NWARP_C) {
        #pragma unroll
        for (int k = 0; k < 4; k++) {
            float v0, v1; unpack2(attp[k], v0, v1);   // rh0, rh1
            v0 += __shfl_xor_sync(0xffffffffu, v0, 1);
            v0 += __shfl_xor_sync(0xffffffffu, v0, 2);
            v1 += __shfl_xor_sync(0xffffffffu, v1, 1);
            v1 += __shfl_xor_sync(0xffffffffu, v1, 2);
            if (t == 0) {
                int s0 = wid * 16 + g;
                if (s0 < S_DIM) atts[k * ATTP + s0] = v0;
                if (s0 + 8 < S_DIM) atts[k * ATTP + s0 + 8] = v1;
            }
        }
    }
    __syncthreads();

    // ---- Phase 4: mask + softmax (one warp per head) ----
    if (tid < 32 * NH) {
        const int k = tid >> 5, l = tid & 31;
        const int* mrow = mask + (size_t)b * S_DIM;
        const float NEGV = -4294967296.0f;
        float mx = -INFINITY;
        for (int s = l; s < S_DIM; s += 32) {
            float v = atts[k * ATTP + s];
            if (mrow[s] == 0) v = NEGV;
            atts[k * ATTP + s] = v;
            mx = fmaxf(mx, v);
        }
        #pragma unroll
        for (int o = 16; o > 0; o >>= 1) mx = fmaxf(mx, __shfl_xor_sync(0xffffffffu, mx, o));
        float sum = 0.0f;
        for (int s = l; s < S_DIM; s += 32) {
            float e = expf(atts[k * ATTP + s] - mx);
            atts[k * ATTP + s] = e;
            sum += e;
        }
        #pragma unroll
        for (int o = 16; o > 0; o >>= 1) sum += __shfl_xor_sync(0xffffffffu, sum, o);
        float inv = 1.0f / sum;
        for (int s = l; s < S_DIM; s += 32) atts[k * ATTP + s] *= inv;
    }
    __syncthreads();

    // ---- Phase 5: interest[k][h] = sum_s att[k][s] * item[b][s][h], 4 s-slices ----
    {
        const int slice = tid >> 7, h = tid & 127;
        const float* ib = itemb + h;
        float a0 = 0.f, a1 = 0.f, a2 = 0.f, a3 = 0.f;
        const int s0 = slice * 50, s1 = s0 + 50;
        #pragma unroll 5
        for (int s = s0; s < s1; s++) {
            float xv = ib[(size_t)s * H_DIM];
            a0 += atts[0 * ATTP + s] * xv;
            a1 += atts[1 * ATTP + s] * xv;
            a2 += atts[2 * ATTP + s] * xv;
            a3 += atts[3 * ATTP + s] * xv;
        }
        if (slice > 0) {
            float* o = outb + (slice - 1) * 512;
            o[0 * 128 + h] = a0; o[1 * 128 + h] = a1;
            o[2 * 128 + h] = a2; o[3 * 128 + h] = a3;
        }
        __syncthreads();
        if (slice == 0) {
            float* ob = out + (size_t)b * (NH * H_DIM);
            #pragma unroll
            for (int k = 0; k < 4; k++) {
                float v = (k == 0 ? a0 : k == 1 ? a1 : k == 2 ? a2 : a3);
                v += outb[0 * 512 + k * 128 + h];
                v += outb[1 * 512 + k * 128 + h];
                v += outb[2 * 512 + k * 128 + h];
                ob[k * H_DIM + h] = v;
            }
        }
    }
}

extern "C" void kernel_launch(void* const* d_in, const int* in_sizes, int n_in,
                              void* d_out, int out_size)
{
    const float* item = (const float*)d_in[0];
    const int*   mask = (const int*)  d_in[1];
    const float* pos  = (const float*)d_in[2];
    const float* W1   = (const float*)d_in[3];
    const float* W2   = (const float*)d_in[4];
    float* out = (float*)d_out;

    const int B = in_sizes[0] / (S_DIM * H_DIM);

    cudaFuncSetAttribute(mha_mma_kernel,
                         cudaFuncAttributeMaxDynamicSharedMemorySize, SM_TOTAL);
    mha_mma_kernel<<<B, NT, SM_TOTAL>>>(item, mask, pos, W1, W2, out);
}

// round 8
// speedup vs baseline: 1.1501x; 1.1501x over previous
#include <cuda_runtime.h>
#include <math.h>
#include <stdint.h>

#define S_DIM 200
#define H_DIM 128
#define F_DIM 512
#define NH 4
#define ATTP 208
#define NT 512
#define NWARP_C 13            // compute warps (M-tile = wid), warps 13-15 produce
#define BUFQ 65536            // one quarter fragment buffer (128 blocks * 512B)

// smem: [buf0 0..64K][buf1 64K..128K][W2 float4 8K][atts][outb]
#define SM_W2    131072
#define SM_ATT   (SM_W2 + 8192)
#define SM_OUTB  (SM_ATT + 3328)
#define SM_TOTAL (SM_OUTB + 6144)   // 148736 B

static __device__ __forceinline__ uint32_t smem_u32(const void* p) {
    uint32_t a;
    asm("{ .reg .u64 t; cvta.to.shared.u64 t, %1; cvt.u32.u64 %0, t; }" : "=r"(a) : "l"(p));
    return a;
}
static __device__ __forceinline__ uint32_t f2tf32(float x) {
    uint32_t r; asm("cvt.rna.tf32.f32 %0, %1;" : "=r"(r) : "f"(x)); return r;
}
static __device__ __forceinline__ float fast_tanh(float x) {
    float r; asm("tanh.approx.f32 %0, %1;" : "=f"(r) : "f"(x));
    return r;
}
static __device__ __forceinline__ void mma_tf32(float* c, const uint32_t* a,
                                                uint32_t b0, uint32_t b1) {
    asm volatile(
        "mma.sync.aligned.m16n8k8.row.col.f32.tf32.tf32.f32 "
        "{%0,%1,%2,%3}, {%4,%5,%6,%7}, {%8,%9}, {%0,%1,%2,%3};"
        : "+f"(c[0]), "+f"(c[1]), "+f"(c[2]), "+f"(c[3])
        : "r"(a[0]), "r"(a[1]), "r"(a[2]), "r"(a[3]), "r"(b0), "r"(b1));
}

// ---- Producer: stage one W1 quarter into a fragment buffer.
// block blk = npair*16 + kf; lane (g,t) 16B slot =
// {W1[kf8+t][n0+g], W1[kf8+t+4][n0+g], W1[kf8+t][n0+8+g], W1[kf8+t+4][n0+8+g]} tf32
static __device__ __forceinline__ void produce_quarter(const float* __restrict__ W1,
                                                       int qcol, uint32_t bufb,
                                                       int pwid, int lane, int g, int t) {
    #pragma unroll 2
    for (int blk = pwid; blk < 128; blk += 3) {
        int npair = blk >> 4, kf = blk & 15;
        const float* p = W1 + (size_t)(kf * 8 + t) * F_DIM + qcol + npair * 16 + g;
        float v0 = p[0];
        float v1 = p[4 * F_DIM];
        float v2 = p[8];
        float v3 = p[8 + 4 * F_DIM];
        uint32_t q0 = f2tf32(v0), q1 = f2tf32(v1), q2 = f2tf32(v2), q3 = f2tf32(v3);
        asm volatile("st.shared.v4.b32 [%0], {%1,%2,%3,%4};"
                     :: "r"(bufb + (uint32_t)blk * 512 + (uint32_t)lane * 16),
                        "r"(q0), "r"(q1), "r"(q2), "r"(q3));
    }
}

// ---- Consumer: one npp sweep (32 N-cols) with fused tanh+W2 epilogue.
static __device__ __forceinline__ void sweep_npp(uint32_t bq, int q, int npp,
                                                 const uint32_t (*A)[4],
                                                 float (*att)[4],
                                                 const float* __restrict__ w2s,
                                                 int lane, int t) {
    float acc[2][2][4];
    #pragma unroll
    for (int p = 0; p < 2; p++)
        #pragma unroll
        for (int nf = 0; nf < 2; nf++)
            #pragma unroll
            for (int i = 0; i < 4; i++) acc[p][nf][i] = 0.0f;

    uint32_t base = bq + (uint32_t)(npp * 32) * 512 + (uint32_t)lane * 16;
    #pragma unroll
    for (int kf = 0; kf < 16; kf++) {
        uint32_t x0, x1, x2, x3, y0, y1, y2, y3;
        uint32_t a0 = base + (uint32_t)kf * 512;
        asm volatile("ld.shared.v4.b32 {%0,%1,%2,%3}, [%4];"
                     : "=r"(x0), "=r"(x1), "=r"(x2), "=r"(x3) : "r"(a0));
        asm volatile("ld.shared.v4.b32 {%0,%1,%2,%3}, [%4];"
                     : "=r"(y0), "=r"(y1), "=r"(y2), "=r"(y3) : "r"(a0 + 8192));
        mma_tf32(acc[0][0], A[kf], x0, x1);
        mma_tf32(acc[0][1], A[kf], x2, x3);
        mma_tf32(acc[1][0], A[kf], y0, y1);
        mma_tf32(acc[1][1], A[kf], y2, y3);
    }
    #pragma unroll
    for (int p = 0; p < 2; p++) {
        #pragma unroll
        for (int nf = 0; nf < 2; nf++) {
            int col0 = q * 128 + (npp * 2 + p) * 16 + nf * 8 + 2 * t;
            float4 wA = ((const float4*)w2s)[col0];
            float4 wB = ((const float4*)w2s)[col0 + 1];
            #pragma unroll
            for (int rh = 0; rh < 2; rh++) {
                float h0 = fast_tanh(acc[p][nf][rh * 2 + 0]);
                float h1 = fast_tanh(acc[p][nf][rh * 2 + 1]);
                att[rh][0] += h0 * wA.x + h1 * wB.x;
                att[rh][1] += h0 * wA.y + h1 * wB.y;
                att[rh][2] += h0 * wA.z + h1 * wB.z;
                att[rh][3] += h0 * wA.w + h1 * wB.w;
            }
        }
    }
}

__global__ __launch_bounds__(NT, 1)
void mha_mma_kernel(const float* __restrict__ item,
                    const int*   __restrict__ mask,
                    const float* __restrict__ pos,
                    const float* __restrict__ W1,
                    const float* __restrict__ W2,
                    float* __restrict__ out)
{
    extern __shared__ char smem[];
    const uint32_t smb = smem_u32(smem);
    float* w2s  = (float*)(smem + SM_W2);
    float* atts = (float*)(smem + SM_ATT);
    float* outb = (float*)(smem + SM_OUTB);

    const int tid = threadIdx.x, wid = tid >> 5, lane = tid & 31;
    const int g = lane >> 2, t = lane & 3;
    const int b = blockIdx.x;
    const float* itemb = item + (size_t)b * (S_DIM * H_DIM);

    // W2 -> smem (1 float4 per thread)
    ((float4*)w2s)[tid] = ((const float4*)W2)[tid];

    // ---- Specialized phase 0: producers stage quarter 0; consumers hoist A from global ----
    uint32_t A[16][4];
    if (wid >= NWARP_C) {
        produce_quarter(W1, 0, smb, wid - NWARP_C, lane, g, t);
    } else {
        const int r0 = wid * 16 + g;
        const float* xr0 = itemb + r0 * 128;
        const float* pr0 = pos + r0 * 128;
        const bool hi = (r0 + 8) < S_DIM;
        const float* xr1 = itemb + (r0 + 8) * 128;
        const float* pr1 = pos + (r0 + 8) * 128;
        #pragma unroll
        for (int kf = 0; kf < 16; kf++) {
            int c0 = kf * 8 + t;
            A[kf][0] = f2tf32(xr0[c0] + pr0[c0]);
            A[kf][2] = f2tf32(xr0[c0 + 4] + pr0[c0 + 4]);
            if (hi) {
                A[kf][1] = f2tf32(xr1[c0] + pr1[c0]);
                A[kf][3] = f2tf32(xr1[c0 + 4] + pr1[c0 + 4]);
            } else {
                A[kf][1] = 0u;
                A[kf][3] = 0u;
            }
        }
    }
    __syncthreads();

    float att[2][4];
    #pragma unroll
    for (int rh = 0; rh < 2; rh++)
        #pragma unroll
        for (int k = 0; k < 4; k++) att[rh][k] = 0.0f;

    // ---- Main loop: producers stage q+1 while consumers sweep q ----
    #pragma unroll 1
    for (int q = 0; q < 4; q++) {
        const uint32_t bq = smb + (uint32_t)(q & 1) * BUFQ;
        if (wid >= NWARP_C) {
            if (q < 3)
                produce_quarter(W1, (q + 1) * 128,
                                smb + (uint32_t)((q + 1) & 1) * BUFQ,
                                wid - NWARP_C, lane, g, t);
        } else {
            sweep_npp(bq, q, 0, A, att, w2s, lane, t);
            sweep_npp(bq, q, 1, A, att, w2s, lane, t);
            sweep_npp(bq, q, 2, A, att, w2s, lane, t);
            sweep_npp(bq, q, 3, A, att, w2s, lane, t);
        }
        __syncthreads();
    }

    // ---- Phase 3: reduce att over the 4-lane k-group, write atts ----
    if (wid < NWARP_C) {
        #pragma unroll
        for (int rh = 0; rh < 2; rh++)
            #pragma unroll
            for (int k = 0; k < 4; k++) {
                float v = att[rh][k];
                v += __shfl_xor_sync(0xffffffffu, v, 1);
                v += __shfl_xor_sync(0xffffffffu, v, 2);
                if (t == 0) {
                    int s = wid * 16 + rh * 8 + g;
                    if (s < S_DIM) atts[k * ATTP + s] = v;
                }
            }
    }
    __syncthreads();

    // ---- Phase 4: mask + softmax (one warp per head) ----
    if (tid < 32 * NH) {
        const int k = tid >> 5, l = tid & 31;
        const int* mrow = mask + (size_t)b * S_DIM;
        const float NEGV = -4294967296.0f;
        float mx = -INFINITY;
        for (int s = l; s < S_DIM; s += 32) {
            float v = atts[k * ATTP + s];
            if (mrow[s] == 0) v = NEGV;
            atts[k * ATTP + s] = v;
            mx = fmaxf(mx, v);
        }
        #pragma unroll
        for (int o = 16; o > 0; o >>= 1) mx = fmaxf(mx, __shfl_xor_sync(0xffffffffu, mx, o));
        float sum = 0.0f;
        for (int s = l; s < S_DIM; s += 32) {
            float e = expf(atts[k * ATTP + s] - mx);
            atts[k * ATTP + s] = e;
            sum += e;
        }
        #pragma unroll
        for (int o = 16; o > 0; o >>= 1) sum += __shfl_xor_sync(0xffffffffu, sum, o);
        float inv = 1.0f / sum;
        for (int s = l; s < S_DIM; s += 32) atts[k * ATTP + s] *= inv;
    }
    __syncthreads();

    // ---- Phase 5: interest[k][h] = sum_s att[k][s] * item[b][s][h], 4 s-slices ----
    {
        const int slice = tid >> 7, h = tid & 127;
        const float* ib = itemb + h;
        float a0 = 0.f, a1 = 0.f, a2 = 0.f, a3 = 0.f;
        const int s0 = slice * 50, s1 = s0 + 50;
        #pragma unroll 5
        for (int s = s0; s < s1; s++) {
            float xv = ib[(size_t)s * H_DIM];
            a0 += atts[0 * ATTP + s] * xv;
            a1 += atts[1 * ATTP + s] * xv;
            a2 += atts[2 * ATTP + s] * xv;
            a3 += atts[3 * ATTP + s] * xv;
        }
        if (slice > 0) {
            float* o = outb + (slice - 1) * 512;
            o[0 * 128 + h] = a0; o[1 * 128 + h] = a1;
            o[2 * 128 + h] = a2; o[3 * 128 + h] = a3;
        }
        __syncthreads();
        if (slice == 0) {
            float* ob = out + (size_t)b * (NH * H_DIM);
            #pragma unroll
            for (int k = 0; k < 4; k++) {
                float v = (k == 0 ? a0 : k == 1 ? a1 : k == 2 ? a2 : a3);
                v += outb[0 * 512 + k * 128 + h];
                v += outb[1 * 512 + k * 128 + h];
                v += outb[2 * 512 + k * 128 + h];
                ob[k * H_DIM + h] = v;
            }
        }
    }
}

extern "C" void kernel_launch(void* const* d_in, const int* in_sizes, int n_in,
                              void* d_out, int out_size)
{
    const float* item = (const float*)d_in[0];
    const int*   mask = (const int*)  d_in[1];
    const float* pos  = (const float*)d_in[2];
    const float* W1   = (const float*)d_in[3];
    const float* W2   = (const float*)d_in[4];
    float* out = (float*)d_out;

    const int B = in_sizes[0] / (S_DIM * H_DIM);

    cudaFuncSetAttribute(mha_mma_kernel,
                         cudaFuncAttributeMaxDynamicSharedMemorySize, SM_TOTAL);
    mha_mma_kernel<<<B, NT, SM_TOTAL>>>(item, mask, pos, W1, W2, out);
}

// round 9
// speedup vs baseline: 1.7169x; 1.4928x over previous
#include <cuda_runtime.h>
#include <cuda_fp16.h>
#include <math.h>
#include <stdint.h>

#define S_DIM 200
#define H_DIM 128
#define F_DIM 512
#define NH 4
#define ATTP 208
#define NT 512
#define NWARP_C 13            // compute warps; warps 13-15 produce
#define BUFQ 32768            // one quarter fp16 fragment buffer (64 blocks * 512B)

// smem: [buf0 0..32K][buf1 32K..64K][W2 float4 8K][atts][outb]
#define SM_W2    65536
#define SM_ATT   (SM_W2 + 8192)
#define SM_OUTB  (SM_ATT + 3328)
#define SM_TOTAL (SM_OUTB + 6144)   // 83200 B

static __device__ __forceinline__ uint32_t smem_u32(const void* p) {
    uint32_t a;
    asm("{ .reg .u64 t; cvta.to.shared.u64 t, %1; cvt.u32.u64 %0, t; }" : "=r"(a) : "l"(p));
    return a;
}
static __device__ __forceinline__ uint32_t h2pack(float lo, float hi) {
    __half2 h = __floats2half2_rn(lo, hi);
    return *(uint32_t*)&h;
}
static __device__ __forceinline__ float fast_tanh(float x) {
    float r; asm("tanh.approx.f32 %0, %1;" : "=f"(r) : "f"(x));
    return r;
}
static __device__ __forceinline__ void mma_f16(float* c, const uint32_t* a,
                                               uint32_t b0, uint32_t b1) {
    asm volatile(
        "mma.sync.aligned.m16n8k16.row.col.f32.f16.f16.f32 "
        "{%0,%1,%2,%3}, {%4,%5,%6,%7}, {%8,%9}, {%0,%1,%2,%3};"
        : "+f"(c[0]), "+f"(c[1]), "+f"(c[2]), "+f"(c[3])
        : "r"(a[0]), "r"(a[1]), "r"(a[2]), "r"(a[3]), "r"(b0), "r"(b1));
}

// ---- Producer: stage one W1 quarter (fp16 fragments).
// block blk = npair*8 + kf16 (npair = 16-col group 0..7, kf16 = 0..7).
// lane (g,t) 16B slot = { h2(W1[kb+2t][c],   W1[kb+2t+1][c]),     // b0, ntile lo
//                         h2(W1[kb+2t+8][c], W1[kb+2t+9][c]),     // b1, ntile lo
//                         h2(W1[kb+2t][c+8], W1[kb+2t+1][c+8]),   // b0, ntile hi
//                         h2(W1[kb+2t+8][c+8],W1[kb+2t+9][c+8]) } // b1, ntile hi
// with kb = kf16*16, c = qcol + npair*16 + g.
static __device__ __forceinline__ void produce_quarter(const float* __restrict__ W1,
                                                       int qcol, uint32_t bufb,
                                                       int pwid, int lane, int g, int t) {
    #pragma unroll 2
    for (int blk = pwid; blk < 64; blk += 3) {
        int npair = blk >> 3, kf = blk & 7;
        const float* p = W1 + (size_t)(kf * 16 + 2 * t) * F_DIM + qcol + npair * 16 + g;
        float a0 = p[0],           b0 = p[F_DIM];
        float c0 = p[8 * F_DIM],   d0 = p[9 * F_DIM];
        float a1 = p[8],           b1 = p[F_DIM + 8];
        float c1 = p[8 * F_DIM + 8], d1 = p[9 * F_DIM + 8];
        uint32_t w0 = h2pack(a0, b0), w1 = h2pack(c0, d0);
        uint32_t w2 = h2pack(a1, b1), w3 = h2pack(c1, d1);
        asm volatile("st.shared.v4.b32 [%0], {%1,%2,%3,%4};"
                     :: "r"(bufb + (uint32_t)blk * 512 + (uint32_t)lane * 16),
                        "r"(w0), "r"(w1), "r"(w2), "r"(w3));
    }
}

// ---- Consumer: one npp sweep (32 N-cols) with fused tanh+W2 epilogue.
static __device__ __forceinline__ void sweep_npp(uint32_t bq, int q, int npp,
                                                 const uint32_t (*A)[4],
                                                 float (*att)[4],
                                                 const float* __restrict__ w2s,
                                                 int lane, int t) {
    float acc[2][2][4];
    #pragma unroll
    for (int p = 0; p < 2; p++)
        #pragma unroll
        for (int nf = 0; nf < 2; nf++)
            #pragma unroll
            for (int i = 0; i < 4; i++) acc[p][nf][i] = 0.0f;

    uint32_t base = bq + (uint32_t)(npp * 16) * 512 + (uint32_t)lane * 16;
    #pragma unroll
    for (int kf = 0; kf < 8; kf++) {
        uint32_t x0, x1, x2, x3, y0, y1, y2, y3;
        uint32_t a0 = base + (uint32_t)kf * 512;
        asm volatile("ld.shared.v4.b32 {%0,%1,%2,%3}, [%4];"
                     : "=r"(x0), "=r"(x1), "=r"(x2), "=r"(x3) : "r"(a0));
        asm volatile("ld.shared.v4.b32 {%0,%1,%2,%3}, [%4];"
                     : "=r"(y0), "=r"(y1), "=r"(y2), "=r"(y3) : "r"(a0 + 4096));
        mma_f16(acc[0][0], A[kf], x0, x1);
        mma_f16(acc[0][1], A[kf], x2, x3);
        mma_f16(acc[1][0], A[kf], y0, y1);
        mma_f16(acc[1][1], A[kf], y2, y3);
    }
    #pragma unroll
    for (int p = 0; p < 2; p++) {
        #pragma unroll
        for (int nf = 0; nf < 2; nf++) {
            int col0 = q * 128 + npp * 32 + p * 16 + nf * 8 + 2 * t;
            float4 wA = ((const float4*)w2s)[col0];
            float4 wB = ((const float4*)w2s)[col0 + 1];
            #pragma unroll
            for (int rh = 0; rh < 2; rh++) {
                float h0 = fast_tanh(acc[p][nf][rh * 2 + 0]);   // row g(+8rh), col 2t
                float h1 = fast_tanh(acc[p][nf][rh * 2 + 1]);   // row g(+8rh), col 2t+1
                att[rh][0] += h0 * wA.x + h1 * wB.x;
                att[rh][1] += h0 * wA.y + h1 * wB.y;
                att[rh][2] += h0 * wA.z + h1 * wB.z;
                att[rh][3] += h0 * wA.w + h1 * wB.w;
            }
        }
    }
}

__global__ __launch_bounds__(NT, 1)
void mha_mma_kernel(const float* __restrict__ item,
                    const int*   __restrict__ mask,
                    const float* __restrict__ pos,
                    const float* __restrict__ W1,
                    const float* __restrict__ W2,
                    float* __restrict__ out)
{
    extern __shared__ char smem[];
    const uint32_t smb = smem_u32(smem);
    float* w2s  = (float*)(smem + SM_W2);
    float* atts = (float*)(smem + SM_ATT);
    float* outb = (float*)(smem + SM_OUTB);

    const int tid = threadIdx.x, wid = tid >> 5, lane = tid & 31;
    const int g = lane >> 2, t = lane & 3;
    const int b = blockIdx.x;
    const float* itemb = item + (size_t)b * (S_DIM * H_DIM);

    // W2 -> smem (1 float4 per thread)
    ((float4*)w2s)[tid] = ((const float4*)W2)[tid];

    // ---- Phase 0 (specialized): producers stage quarter 0; consumers hoist A (fp16) ----
    // m16n8k16 A fragment, kf16-block kf: a0={X[r0][c0],X[r0][c0+1]},
    // a1={X[r0+8][c0..]}, a2={X[r0][c0+8..]}, a3={X[r0+8][c0+8..]}, c0=kf*16+2t.
    uint32_t A[8][4];
    if (wid >= NWARP_C) {
        produce_quarter(W1, 0, smb, wid - NWARP_C, lane, g, t);
    } else {
        const int r0 = wid * 16 + g;
        const float2* xr0 = (const float2*)(itemb + r0 * 128);
        const float2* pr0 = (const float2*)(pos + r0 * 128);
        const bool hi = (r0 + 8) < S_DIM;
        const float2* xr1 = (const float2*)(itemb + (r0 + 8) * 128);
        const float2* pr1 = (const float2*)(pos + (r0 + 8) * 128);
        #pragma unroll
        for (int kf = 0; kf < 8; kf++) {
            int e0 = kf * 8 + t;          // float2 index of cols (kf*16+2t, +1)
            float2 x0 = xr0[e0], p0 = pr0[e0];
            float2 x2 = xr0[e0 + 4], p2 = pr0[e0 + 4];
            A[kf][0] = h2pack(x0.x + p0.x, x0.y + p0.y);
            A[kf][2] = h2pack(x2.x + p2.x, x2.y + p2.y);
            if (hi) {
                float2 x1 = xr1[e0], p1 = pr1[e0];
                float2 x3 = xr1[e0 + 4], p3 = pr1[e0 + 4];
                A[kf][1] = h2pack(x1.x + p1.x, x1.y + p1.y);
                A[kf][3] = h2pack(x3.x + p3.x, x3.y + p3.y);
            } else {
                A[kf][1] = 0u;
                A[kf][3] = 0u;
            }
        }
    }
    __syncthreads();

    float att[2][4];
    #pragma unroll
    for (int rh = 0; rh < 2; rh++)
        #pragma unroll
        for (int k = 0; k < 4; k++) att[rh][k] = 0.0f;

    // ---- Main loop: producers stage q+1 while consumers sweep q ----
    #pragma unroll 1
    for (int q = 0; q < 4; q++) {
        const uint32_t bq = smb + (uint32_t)(q & 1) * BUFQ;
        if (wid >= NWARP_C) {
            if (q < 3)
                produce_quarter(W1, (q + 1) * 128,
                                smb + (uint32_t)((q + 1) & 1) * BUFQ,
                                wid - NWARP_C, lane, g, t);
        } else {
            sweep_npp(bq, q, 0, A, att, w2s, lane, t);
            sweep_npp(bq, q, 1, A, att, w2s, lane, t);
            sweep_npp(bq, q, 2, A, att, w2s, lane, t);
            sweep_npp(bq, q, 3, A, att, w2s, lane, t);
        }
        __syncthreads();
    }

    // ---- Phase 3: reduce att over the 4-lane k-group, write atts ----
    if (wid < NWARP_C) {
        #pragma unroll
        for (int rh = 0; rh < 2; rh++)
            #pragma unroll
            for (int k = 0; k < 4; k++) {
                float v = att[rh][k];
                v += __shfl_xor_sync(0xffffffffu, v, 1);
                v += __shfl_xor_sync(0xffffffffu, v, 2);
                if (t == 0) {
                    int s = wid * 16 + rh * 8 + g;
                    if (s < S_DIM) atts[k * ATTP + s] = v;
                }
            }
    }
    __syncthreads();

    // ---- Phase 4: mask + softmax (one warp per head) ----
    if (tid < 32 * NH) {
        const int k = tid >> 5, l = tid & 31;
        const int* mrow = mask + (size_t)b * S_DIM;
        const float NEGV = -4294967296.0f;
        float mx = -INFINITY;
        for (int s = l; s < S_DIM; s += 32) {
            float v = atts[k * ATTP + s];
            if (mrow[s] == 0) v = NEGV;
            atts[k * ATTP + s] = v;
            mx = fmaxf(mx, v);
        }
        #pragma unroll
        for (int o = 16; o > 0; o >>= 1) mx = fmaxf(mx, __shfl_xor_sync(0xffffffffu, mx, o));
        float sum = 0.0f;
        for (int s = l; s < S_DIM; s += 32) {
            float e = expf(atts[k * ATTP + s] - mx);
            atts[k * ATTP + s] = e;
            sum += e;
        }
        #pragma unroll
        for (int o = 16; o > 0; o >>= 1) sum += __shfl_xor_sync(0xffffffffu, sum, o);
        float inv = 1.0f / sum;
        for (int s = l; s < S_DIM; s += 32) atts[k * ATTP + s] *= inv;
    }
    __syncthreads();

    // ---- Phase 5: interest[k][h] = sum_s att[k][s] * item[b][s][h], 4 s-slices ----
    {
        const int slice = tid >> 7, h = tid & 127;
        const float* ib = itemb + h;
        float a0 = 0.f, a1 = 0.f, a2 = 0.f, a3 = 0.f;
        const int s0 = slice * 50, s1 = s0 + 50;
        #pragma unroll 5
        for (int s = s0; s < s1; s++) {
            float xv = ib[(size_t)s * H_DIM];
            a0 += atts[0 * ATTP + s] * xv;
            a1 += atts[1 * ATTP + s] * xv;
            a2 += atts[2 * ATTP + s] * xv;
            a3 += atts[3 * ATTP + s] * xv;
        }
        if (slice > 0) {
            float* o = outb + (slice - 1) * 512;
            o[0 * 128 + h] = a0; o[1 * 128 + h] = a1;
            o[2 * 128 + h] = a2; o[3 * 128 + h] = a3;
        }
        __syncthreads();
        if (slice == 0) {
            float* ob = out + (size_t)b * (NH * H_DIM);
            #pragma unroll
            for (int k = 0; k < 4; k++) {
                float v = (k == 0 ? a0 : k == 1 ? a1 : k == 2 ? a2 : a3);
                v += outb[0 * 512 + k * 128 + h];
                v += outb[1 * 512 + k * 128 + h];
                v += outb[2 * 512 + k * 128 + h];
                ob[k * H_DIM + h] = v;
            }
        }
    }
}

extern "C" void kernel_launch(void* const* d_in, const int* in_sizes, int n_in,
                              void* d_out, int out_size)
{
    const float* item = (const float*)d_in[0];
    const int*   mask = (const int*)  d_in[1];
    const float* pos  = (const float*)d_in[2];
    const float* W1   = (const float*)d_in[3];
    const float* W2   = (const float*)d_in[4];
    float* out = (float*)d_out;

    const int B = in_sizes[0] / (S_DIM * H_DIM);

    cudaFuncSetAttribute(mha_mma_kernel,
                         cudaFuncAttributeMaxDynamicSharedMemorySize, SM_TOTAL);
    mha_mma_kernel<<<B, NT, SM_TOTAL>>>(item, mask, pos, W1, W2, out);
}

// round 10
// speedup vs baseline: 2.3636x; 1.3767x over previous
#include <cuda_runtime.h>
#include <cuda_fp16.h>
#include <math.h>
#include <stdint.h>

#define S_DIM 200
#define H_DIM 128
#define F_DIM 512
#define NH 4
#define ATTP 208
#define NT 512
#define NWARP_C 13            // compute warps; warps 13-15 produce
#define BUFQ 32768            // one quarter fp16 fragment buffer (64 blocks * 512B)

// smem: [buf0 0..32K][buf1 32K..64K][W2 float4 8K][atts 2x][outb 2x]
#define SM_W2    65536
#define SM_ATT   (SM_W2 + 8192)          // 2 * 4 * 208 floats = 6656 B
#define SM_OUTB  (SM_ATT + 6656)         // 2 * 512 floats = 4096 B
#define SM_TOTAL (SM_OUTB + 4096)        // 84480 B

static __device__ __forceinline__ uint32_t smem_u32(const void* p) {
    uint32_t a;
    asm("{ .reg .u64 t; cvta.to.shared.u64 t, %1; cvt.u32.u64 %0, t; }" : "=r"(a) : "l"(p));
    return a;
}
static __device__ __forceinline__ uint32_t h2pack(float lo, float hi) {
    __half2 h = __floats2half2_rn(lo, hi);
    return *(uint32_t*)&h;
}
static __device__ __forceinline__ float fast_tanh(float x) {
    float r; asm("tanh.approx.f32 %0, %1;" : "=f"(r) : "f"(x));
    return r;
}
static __device__ __forceinline__ void mma_f16(float* c, const uint32_t* a,
                                               uint32_t b0, uint32_t b1) {
    asm volatile(
        "mma.sync.aligned.m16n8k16.row.col.f32.f16.f16.f32 "
        "{%0,%1,%2,%3}, {%4,%5,%6,%7}, {%8,%9}, {%0,%1,%2,%3};"
        : "+f"(c[0]), "+f"(c[1]), "+f"(c[2]), "+f"(c[3])
        : "r"(a[0]), "r"(a[1]), "r"(a[2]), "r"(a[3]), "r"(b0), "r"(b1));
}

// ---- Producer: stage one W1 quarter (fp16 fragments), identical layout to R9.
// block blk = npair*8 + kf16; lane (g,t) 16B slot holds the two ntiles' (b0,b1) pairs.
static __device__ __forceinline__ void produce_quarter(const float* __restrict__ W1,
                                                       int qcol, uint32_t bufb,
                                                       int pwid, int lane, int g, int t) {
    #pragma unroll 2
    for (int blk = pwid; blk < 64; blk += 3) {
        int npair = blk >> 3, kf = blk & 7;
        const float* p = W1 + (size_t)(kf * 16 + 2 * t) * F_DIM + qcol + npair * 16 + g;
        float a0 = p[0],             b0 = p[F_DIM];
        float c0 = p[8 * F_DIM],     d0 = p[9 * F_DIM];
        float a1 = p[8],             b1 = p[F_DIM + 8];
        float c1 = p[8 * F_DIM + 8], d1 = p[9 * F_DIM + 8];
        uint32_t w0 = h2pack(a0, b0), w1 = h2pack(c0, d0);
        uint32_t w2 = h2pack(a1, b1), w3 = h2pack(c1, d1);
        asm volatile("st.shared.v4.b32 [%0], {%1,%2,%3,%4};"
                     :: "r"(bufb + (uint32_t)blk * 512 + (uint32_t)lane * 16),
                        "r"(w0), "r"(w1), "r"(w2), "r"(w3));
    }
}

// ---- Consumer: one half-sweep (16 N-cols) for BOTH batches; B regs reused 4x.
static __device__ __forceinline__ void sweep_half(uint32_t bq, int q, int hs,
                                                  const uint32_t A[2][8][4],
                                                  float att[2][2][4],
                                                  const float* __restrict__ w2s,
                                                  int lane, int t) {
    float acc[2][2][4];   // [batch][ntile][4]
    #pragma unroll
    for (int bb = 0; bb < 2; bb++)
        #pragma unroll
        for (int nf = 0; nf < 2; nf++)
            #pragma unroll
            for (int i = 0; i < 4; i++) acc[bb][nf][i] = 0.0f;

    uint32_t base = bq + (uint32_t)(hs * 8) * 512 + (uint32_t)lane * 16;
    #pragma unroll
    for (int kf = 0; kf < 8; kf++) {
        uint32_t x0, x1, x2, x3;
        asm volatile("ld.shared.v4.b32 {%0,%1,%2,%3}, [%4];"
                     : "=r"(x0), "=r"(x1), "=r"(x2), "=r"(x3)
                     : "r"(base + (uint32_t)kf * 512));
        mma_f16(acc[0][0], A[0][kf], x0, x1);
        mma_f16(acc[0][1], A[0][kf], x2, x3);
        mma_f16(acc[1][0], A[1][kf], x0, x1);
        mma_f16(acc[1][1], A[1][kf], x2, x3);
    }
    #pragma unroll
    for (int nf = 0; nf < 2; nf++) {
        int col0 = q * 128 + hs * 16 + nf * 8 + 2 * t;
        float4 wA = ((const float4*)w2s)[col0];
        float4 wB = ((const float4*)w2s)[col0 + 1];
        #pragma unroll
        for (int bb = 0; bb < 2; bb++) {
            #pragma unroll
            for (int rh = 0; rh < 2; rh++) {
                float h0 = fast_tanh(acc[bb][nf][rh * 2 + 0]);   // col 2t
                float h1 = fast_tanh(acc[bb][nf][rh * 2 + 1]);   // col 2t+1
                att[bb][rh][0] += h0 * wA.x + h1 * wB.x;
                att[bb][rh][1] += h0 * wA.y + h1 * wB.y;
                att[bb][rh][2] += h0 * wA.z + h1 * wB.z;
                att[bb][rh][3] += h0 * wA.w + h1 * wB.w;
            }
        }
    }
}

__global__ __launch_bounds__(NT, 1)
void mha_mma_kernel(const float* __restrict__ item,
                    const int*   __restrict__ mask,
                    const float* __restrict__ pos,
                    const float* __restrict__ W1,
                    const float* __restrict__ W2,
                    float* __restrict__ out)
{
    extern __shared__ char smem[];
    const uint32_t smb = smem_u32(smem);
    float* w2s  = (float*)(smem + SM_W2);
    float* atts = (float*)(smem + SM_ATT);   // [2][NH][ATTP]
    float* outb = (float*)(smem + SM_OUTB);  // [2][512]

    const int tid = threadIdx.x, wid = tid >> 5, lane = tid & 31;
    const int g = lane >> 2, t = lane & 3;
    const int b0 = 2 * blockIdx.x;

    // W2 -> smem (1 float4 per thread)
    ((float4*)w2s)[tid] = ((const float4*)W2)[tid];

    // ---- Phase 0 (specialized): producers stage quarter 0; consumers hoist A (fp16, both batches) ----
    uint32_t A[2][8][4];
    if (wid >= NWARP_C) {
        produce_quarter(W1, 0, smb, wid - NWARP_C, lane, g, t);
    } else {
        const int r0 = wid * 16 + g;
        const bool hi = (r0 + 8) < S_DIM;
        #pragma unroll
        for (int bb = 0; bb < 2; bb++) {
            const float* ib = item + (size_t)(b0 + bb) * (S_DIM * H_DIM);
            const float2* xr0 = (const float2*)(ib + r0 * 128);
            const float2* pr0 = (const float2*)(pos + r0 * 128);
            const float2* xr1 = (const float2*)(ib + (r0 + 8) * 128);
            const float2* pr1 = (const float2*)(pos + (r0 + 8) * 128);
            #pragma unroll
            for (int kf = 0; kf < 8; kf++) {
                int e0 = kf * 8 + t;
                float2 x0 = xr0[e0], p0 = pr0[e0];
                float2 x2 = xr0[e0 + 4], p2 = pr0[e0 + 4];
                A[bb][kf][0] = h2pack(x0.x + p0.x, x0.y + p0.y);
                A[bb][kf][2] = h2pack(x2.x + p2.x, x2.y + p2.y);
                if (hi) {
                    float2 x1 = xr1[e0], p1 = pr1[e0];
                    float2 x3 = xr1[e0 + 4], p3 = pr1[e0 + 4];
                    A[bb][kf][1] = h2pack(x1.x + p1.x, x1.y + p1.y);
                    A[bb][kf][3] = h2pack(x3.x + p3.x, x3.y + p3.y);
                } else {
                    A[bb][kf][1] = 0u;
                    A[bb][kf][3] = 0u;
                }
            }
        }
    }
    __syncthreads();

    float att[2][2][4];
    #pragma unroll
    for (int bb = 0; bb < 2; bb++)
        #pragma unroll
        for (int rh = 0; rh < 2; rh++)
            #pragma unroll
            for (int k = 0; k < 4; k++) att[bb][rh][k] = 0.0f;

    // ---- Main loop: producers stage q+1 while consumers run 8 half-sweeps of q ----
    #pragma unroll 1
    for (int q = 0; q < 4; q++) {
        const uint32_t bq = smb + (uint32_t)(q & 1) * BUFQ;
        if (wid >= NWARP_C) {
            if (q < 3)
                produce_quarter(W1, (q + 1) * 128,
                                smb + (uint32_t)((q + 1) & 1) * BUFQ,
                                wid - NWARP_C, lane, g, t);
        } else {
            #pragma unroll 1
            for (int hs = 0; hs < 8; hs++)
                sweep_half(bq, q, hs, A, att, w2s, lane, t);
        }
        __syncthreads();
    }

    // ---- Phase 3: reduce att over the 4-lane k-group, write atts (both batches) ----
    if (wid < NWARP_C) {
        #pragma unroll
        for (int bb = 0; bb < 2; bb++)
            #pragma unroll
            for (int rh = 0; rh < 2; rh++)
                #pragma unroll
                for (int k = 0; k < 4; k++) {
                    float v = att[bb][rh][k];
                    v += __shfl_xor_sync(0xffffffffu, v, 1);
                    v += __shfl_xor_sync(0xffffffffu, v, 2);
                    if (t == 0) {
                        int s = wid * 16 + rh * 8 + g;
                        if (s < S_DIM) atts[bb * NH * ATTP + k * ATTP + s] = v;
                    }
                }
    }
    __syncthreads();

    // ---- Phase 4: mask + softmax (one warp per (batch, head)) ----
    if (tid < 32 * NH * 2) {
        const int bb = tid >> 7, k = (tid >> 5) & 3, l = tid & 31;
        float* ar = atts + bb * NH * ATTP + k * ATTP;
        const int* mrow = mask + (size_t)(b0 + bb) * S_DIM;
        const float NEGV = -4294967296.0f;
        float mx = -INFINITY;
        for (int s = l; s < S_DIM; s += 32) {
            float v = ar[s];
            if (mrow[s] == 0) v = NEGV;
            ar[s] = v;
            mx = fmaxf(mx, v);
        }
        #pragma unroll
        for (int o = 16; o > 0; o >>= 1) mx = fmaxf(mx, __shfl_xor_sync(0xffffffffu, mx, o));
        float sum = 0.0f;
        for (int s = l; s < S_DIM; s += 32) {
            float e = expf(ar[s] - mx);
            ar[s] = e;
            sum += e;
        }
        #pragma unroll
        for (int o = 16; o > 0; o >>= 1) sum += __shfl_xor_sync(0xffffffffu, sum, o);
        float inv = 1.0f / sum;
        for (int s = l; s < S_DIM; s += 32) ar[s] *= inv;
    }
    __syncthreads();

    // ---- Phase 5: interest[k][h] = sum_s att[k][s] * item[b][s][h]; 2 batches x 2 s-slices ----
    {
        const int bb = tid >> 8, rem = tid & 255;
        const int slice = rem >> 7, h = rem & 127;
        const float* ib = item + (size_t)(b0 + bb) * (S_DIM * H_DIM) + h;
        const float* ar = atts + bb * NH * ATTP;
        float a0 = 0.f, a1 = 0.f, a2 = 0.f, a3 = 0.f;
        const int s0 = slice * 100, s1 = s0 + 100;
        #pragma unroll 4
        for (int s = s0; s < s1; s++) {
            float xv = ib[(size_t)s * H_DIM];
            a0 += ar[0 * ATTP + s] * xv;
            a1 += ar[1 * ATTP + s] * xv;
            a2 += ar[2 * ATTP + s] * xv;
            a3 += ar[3 * ATTP + s] * xv;
        }
        if (slice == 1) {
            float* o = outb + bb * 512;
            o[0 * 128 + h] = a0; o[1 * 128 + h] = a1;
            o[2 * 128 + h] = a2; o[3 * 128 + h] = a3;
        }
        __syncthreads();
        if (slice == 0) {
            float* ob = out + (size_t)(b0 + bb) * (NH * H_DIM);
            const float* o = outb + bb * 512;
            ob[0 * H_DIM + h] = a0 + o[0 * 128 + h];
            ob[1 * H_DIM + h] = a1 + o[1 * 128 + h];
            ob[2 * H_DIM + h] = a2 + o[2 * 128 + h];
            ob[3 * H_DIM + h] = a3 + o[3 * 128 + h];
        }
    }
}

extern "C" void kernel_launch(void* const* d_in, const int* in_sizes, int n_in,
                              void* d_out, int out_size)
{
    const float* item = (const float*)d_in[0];
    const int*   mask = (const int*)  d_in[1];
    const float* pos  = (const float*)d_in[2];
    const float* W1   = (const float*)d_in[3];
    const float* W2   = (const float*)d_in[4];
    float* out = (float*)d_out;

    const int B = in_sizes[0] / (S_DIM * H_DIM);

    cudaFuncSetAttribute(mha_mma_kernel,
                         cudaFuncAttributeMaxDynamicSharedMemorySize, SM_TOTAL);
    mha_mma_kernel<<<B / 2, NT, SM_TOTAL>>>(item, mask, pos, W1, W2, out);
}